// round 9
// baseline (speedup 1.0000x reference)
#include <cuda_runtime.h>

// Problem constants
#define Bc 64
#define Kc 5
#define Hc 320
#define Wc 320
#define Nc (Hc * Wc)        // 102400 pixels per (b,k)
#define NGc (Nc / 4)        // 25600 float4 groups
#define BPB 25              // blocks per batch; each block owns 1024 groups
#define THREADS 256
#define TOTAL_BLOCKS (Bc * BPB)
#define NACC 23             // 5*(S,I,XS,XF) + spsum + tabs + tfg
#define ROW 24              // scratch row stride (floats)

// Per-block partial sums: [b*BPB+block][ROW]. Overwritten every launch.
__device__ float g_scratch[TOTAL_BLOCKS * ROW];
// Per-batch losses.
__device__ float g_loss[Bc];
// Two-level last-block-done counters. atomicInc with limit L-1 wraps to 0
// after exactly L increments -> self-resetting across graph replays.
__device__ unsigned int g_cnt_b[Bc];   // wraps at BPB
__device__ unsigned int g_cnt;         // wraps at Bc

// Per-element update. 3 MUFU (EX2, RCP, LG2): ~23us of MUFU-pipe time chip-wide,
// fma pipe ~21us, DRAM ~25us -- memory is the binding pipe.
// BCE identity: sum max(x,0) = 0.5*(sum x + sum |x|) -> no per-k softplus acc.
__device__ __forceinline__ void elem(float x, float fg,
                                     float& S, float& I, float& XS, float& XF,
                                     float& spsum, float& tabs)
{
    const float t  = fabsf(x);
    const float e  = __expf(-t);                 // FMUL + MUFU.EX2
    const float u  = 1.0f + e;
    const float rc = __fdividef(1.0f, u);        // MUFU.RCP
    const float p  = (x >= 0.0f) ? rc : (1.0f - rc);   // sigmoid(x)
    const float sp = __logf(u);                  // log1p(e) = MUFU.LG2 + FMUL

    spsum += sp;
    tabs  += t;
    S     += p;
    I      = fmaf(p, fg, I);
    XS    += x;
    XF     = fmaf(x, fg, XF);
}

#define ELEM4(xv, fgv, k) \
    elem((xv).x, (fgv).x, acc[(k)*4+0], acc[(k)*4+1], acc[(k)*4+2], acc[(k)*4+3], acc[20], acc[21]); \
    elem((xv).y, (fgv).y, acc[(k)*4+0], acc[(k)*4+1], acc[(k)*4+2], acc[(k)*4+3], acc[20], acc[21]); \
    elem((xv).z, (fgv).z, acc[(k)*4+0], acc[(k)*4+1], acc[(k)*4+2], acc[(k)*4+3], acc[20], acc[21]); \
    elem((xv).w, (fgv).w, acc[(k)*4+0], acc[(k)*4+1], acc[(k)*4+2], acc[(k)*4+3], acc[20], acc[21]);

// __launch_bounds__(256, 2): explicit 2-CTA/SM target -> 128-reg budget.
// Without it, fusing the finalize tail tipped ptxas into a 48-reg allocation
// that serialized the 12-load batch (R5/R7: ~47us @ 3.4TB/s). The hot loop
// needs ~95 regs for the loads to actually be in flight.
__global__ __launch_bounds__(THREADS, 2)
void hung_fused(const float* __restrict__ slot, const float* __restrict__ tgt,
                float* __restrict__ out)
{
    const int b = blockIdx.y;
    const int tid = threadIdx.x;

    float acc[NACC];
#pragma unroll
    for (int i = 0; i < NACC; i++) acc[i] = 0.0f;

    const float4* tg4 = reinterpret_cast<const float4*>(tgt) + (size_t)b * NGc;
    const float4* sl4 = reinterpret_cast<const float4*>(slot) + (size_t)b * Kc * NGc;

    const int base = blockIdx.x * (NGc / BPB);   // 1024 groups per block

    // Two iterations; each explicitly batches 12 independent LDG.128s before
    // any compute (MLP=12). unroll 1 stops ptxas from merging iterations into
    // a 24-deep front batch (L1tex-queue contention, R4 = 54us).
#pragma unroll 1
    for (int it = 0; it < 2; it++) {
        const int g0 = base + it * (2 * THREADS) + tid;
        const int g1 = g0 + THREADS;

        const float4 fgA = __ldg(&tg4[g0]);
        const float4 fgB = __ldg(&tg4[g1]);
        float4 xa[Kc], xb[Kc];
#pragma unroll
        for (int k = 0; k < Kc; k++) {
            xa[k] = __ldg(&sl4[(size_t)k * NGc + g0]);
            xb[k] = __ldg(&sl4[(size_t)k * NGc + g1]);
        }

        acc[22] += ((fgA.x + fgA.y) + (fgA.z + fgA.w))
                 + ((fgB.x + fgB.y) + (fgB.z + fgB.w));   // tfg
#pragma unroll
        for (int k = 0; k < Kc; k++) {
            ELEM4(xa[k], fgA, k)
            ELEM4(xb[k], fgB, k)
        }
    }

    // Block reduction: warp shuffle then cross-warp via shared (deterministic).
#pragma unroll
    for (int i = 0; i < NACC; i++) {
        float v = acc[i];
#pragma unroll
        for (int o = 16; o > 0; o >>= 1) v += __shfl_xor_sync(0xffffffffu, v, o);
        acc[i] = v;
    }
    __shared__ float sm[THREADS / 32][NACC];
    __shared__ float colsum[NACC];
    const int warp = tid >> 5, lane = tid & 31;
    if (lane == 0) {
#pragma unroll
        for (int i = 0; i < NACC; i++) sm[warp][i] = acc[i];
    }
    __syncthreads();
    if (tid < NACC) {
        float s = 0.0f;
#pragma unroll
        for (int w = 0; w < THREADS / 32; w++) s += sm[w][tid];
        colsum[tid] = s;
    }
    __syncthreads();

    // Publish this block's partials; bump the PER-BATCH counter.
    __shared__ unsigned int s_lastb;
    if (tid == 0) {
        float* dst = &g_scratch[((size_t)b * BPB + blockIdx.x) * ROW];
#pragma unroll
        for (int i = 0; i < NACC; i++) dst[i] = colsum[i];
        __threadfence();
        s_lastb = (atomicInc(&g_cnt_b[b], BPB - 1) == BPB - 1) ? 1u : 0u;
    }
    __syncthreads();
    if (s_lastb == 0u) return;

    // ---- Last block of batch b: reduce this batch's 25 partial rows (~2.3KB,
    // L2-hot) and compute loss_b. Runs after hot-loop registers are dead. ----
    __threadfence();   // acquire side
    __shared__ float sa[NACC];
    if (tid < NACC) {
        float v = 0.0f;
#pragma unroll
        for (int j = 0; j < BPB; j++)
            v += __ldcg(&g_scratch[((size_t)b * BPB + j) * ROW + tid]);
        sa[tid] = v;
    }
    __syncthreads();

    __shared__ unsigned int s_lastg;
    if (tid == 0) {
        const float* a = sa;
        const float Tfg   = a[22];
        const float Tbg   = (float)Nc - Tfg;
        const float spsum = a[20];
        const float tabs  = a[21];
        float sumXS = 0.0f, sumXF = 0.0f;
        float best = 3.4e38f, selXS = 0.0f, selXF = 0.0f;
#pragma unroll
        for (int k = 0; k < Kc; k++) {
            const float S  = a[k*4+0];
            const float I  = a[k*4+1];
            const float XS = a[k*4+2];
            const float XF = a[k*4+3];
            const float Ib = S - I;
            const float cfg = 1.0f - I  / (S + Tfg - I  + 1e-6f);
            const float cbg = 1.0f - Ib / (S + Tbg - Ib + 1e-6f);
            const float score = cfg - cbg;   // perm cost differs only by this term
            if (score < best) { best = score; selXS = XS; selXF = XF; }  // ties -> smallest k
            sumXS += XS; sumXF += XF;
        }
        const float Ctot = spsum + 0.5f * (sumXS + tabs);  // sum max(x,0) + sum softplus
        // loss_b = Ctot - [XF_k0 + sum_{k!=k0}(XS_k - XF_k)]
        g_loss[b] = Ctot - sumXS + sumXF + selXS - 2.0f * selXF;
        __threadfence();
        s_lastg = (atomicInc(&g_cnt, Bc - 1) == Bc - 1) ? 1u : 0u;
    }
    __syncthreads();
    if (s_lastg == 0u) return;

    // ---- Globally last finisher: sum the 64 per-batch losses. ----
    __threadfence();   // acquire side
    float l = (tid < Bc) ? __ldcg(&g_loss[tid]) : 0.0f;
#pragma unroll
    for (int o = 16; o > 0; o >>= 1) l += __shfl_xor_sync(0xffffffffu, l, o);
    __shared__ float wsum[THREADS / 32];
    if ((tid & 31) == 0) wsum[tid >> 5] = l;
    __syncthreads();
    if (tid == 0)
        out[0] = (wsum[0] + wsum[1]) * (1.0f / ((float)Bc * (float)Kc * (float)Nc));
}

extern "C" void kernel_launch(void* const* d_in, const int* in_sizes, int n_in,
                              void* d_out, int out_size)
{
    // metadata order: fg_logits (unused by reference), slot_logits, target
    const float* slot = (const float*)d_in[1];
    const float* tgt  = (const float*)d_in[2];
    float* out = (float*)d_out;

    dim3 grid(BPB, Bc);
    hung_fused<<<grid, THREADS>>>(slot, tgt, out);
}

// round 10
// speedup vs baseline: 1.1641x; 1.1641x over previous
#include <cuda_runtime.h>

// Problem constants
#define Bc 64
#define Kc 5
#define Hc 320
#define Wc 320
#define Nc (Hc * Wc)        // 102400 pixels per (b,k)
#define NGc (Nc / 4)        // 25600 float4 groups
#define BPB 25              // blocks per batch; each block owns 1024 groups
#define THREADS 256
#define TOTAL_BLOCKS (Bc * BPB)
#define NACC 23             // 5*(S,I,XS,XF) + spsum + tabs + tfg
#define ROW 24              // scratch row stride (floats)

// Per-block partial sums: [b*BPB+block][ROW]. Overwritten every launch.
__device__ float g_scratch[TOTAL_BLOCKS * ROW];
// Per-batch losses + last-block counter for the finalize kernel.
__device__ float g_loss[Bc];
// atomicInc with limit Bc-1 wraps to 0 after exactly Bc increments ->
// self-resetting across graph replays.
__device__ unsigned int g_cnt = 0;

// Per-element update. 2 MUFU (EX2, LG2) ~= 14us chip-wide; the reciprocal
// 1/(1+e) runs on the fma pipe (seed 48/17 - 32/17*u + 2 Newton steps,
// rel err ~1.2e-5 on u in (1,2]). p feeds ONLY the argmin selection (S,I never
// enter the loss value), so this precision is ample. DRAM (~23us) is now the
// single binding pipe.
// BCE identity: sum max(x,0) = 0.5*(sum x + sum |x|) -> no per-k softplus acc.
__device__ __forceinline__ void elem(float x, float fg,
                                     float& S, float& I, float& XS, float& XF,
                                     float& spsum, float& tabs)
{
    const float t  = fabsf(x);
    const float e  = __expf(-t);                 // FMUL + MUFU.EX2
    const float u  = 1.0f + e;
    float rc = fmaf(u, -1.88235294f, 2.82352941f);   // 48/17 - 32/17*u
    rc = rc * fmaf(-u, rc, 2.0f);                // Newton 1
    rc = rc * fmaf(-u, rc, 2.0f);                // Newton 2
    const float p  = (x >= 0.0f) ? rc : (1.0f - rc);   // sigmoid(x)
    const float sp = __logf(u);                  // log1p(e) = MUFU.LG2 + FMUL

    spsum += sp;
    tabs  += t;
    S     += p;
    I      = fmaf(p, fg, I);
    XS    += x;
    XF     = fmaf(x, fg, XF);
}

#define ELEM4(xv, fgv, k) \
    elem((xv).x, (fgv).x, acc[(k)*4+0], acc[(k)*4+1], acc[(k)*4+2], acc[(k)*4+3], acc[20], acc[21]); \
    elem((xv).y, (fgv).y, acc[(k)*4+0], acc[(k)*4+1], acc[(k)*4+2], acc[(k)*4+3], acc[20], acc[21]); \
    elem((xv).z, (fgv).z, acc[(k)*4+0], acc[(k)*4+1], acc[(k)*4+2], acc[(k)*4+3], acc[20], acc[21]); \
    elem((xv).w, (fgv).w, acc[(k)*4+0], acc[(k)*4+1], acc[(k)*4+2], acc[(k)*4+3], acc[20], acc[21]);

// Hot-loop kernel: MUST stay standalone with NO launch_bounds min-blocks.
// Fused variants either got regs=48 (loads serialized, 47us) or regs=128
// (occ 23%, 43us). This shape is the proven ~30us artifact.
__global__ __launch_bounds__(THREADS)
void hung_main(const float* __restrict__ slot, const float* __restrict__ tgt)
{
    const int b = blockIdx.y;
    const int tid = threadIdx.x;

    float acc[NACC];
#pragma unroll
    for (int i = 0; i < NACC; i++) acc[i] = 0.0f;

    const float4* tg4 = reinterpret_cast<const float4*>(tgt) + (size_t)b * NGc;
    const float4* sl4 = reinterpret_cast<const float4*>(slot) + (size_t)b * Kc * NGc;

    const int base = blockIdx.x * (NGc / BPB);   // 1024 groups per block

    // Two iterations; each explicitly batches 12 independent LDG.128s before
    // any compute (MLP=12). unroll 1 stops ptxas from merging iterations into
    // a 24-deep front batch (L1tex-queue contention, R4 = 54us).
#pragma unroll 1
    for (int it = 0; it < 2; it++) {
        const int g0 = base + it * (2 * THREADS) + tid;
        const int g1 = g0 + THREADS;

        const float4 fgA = __ldg(&tg4[g0]);
        const float4 fgB = __ldg(&tg4[g1]);
        float4 xa[Kc], xb[Kc];
#pragma unroll
        for (int k = 0; k < Kc; k++) {
            xa[k] = __ldg(&sl4[(size_t)k * NGc + g0]);
            xb[k] = __ldg(&sl4[(size_t)k * NGc + g1]);
        }

        acc[22] += ((fgA.x + fgA.y) + (fgA.z + fgA.w))
                 + ((fgB.x + fgB.y) + (fgB.z + fgB.w));   // tfg
#pragma unroll
        for (int k = 0; k < Kc; k++) {
            ELEM4(xa[k], fgA, k)
            ELEM4(xb[k], fgB, k)
        }
    }

    // Block reduction: warp shuffle then cross-warp via shared (deterministic).
#pragma unroll
    for (int i = 0; i < NACC; i++) {
        float v = acc[i];
#pragma unroll
        for (int o = 16; o > 0; o >>= 1) v += __shfl_xor_sync(0xffffffffu, v, o);
        acc[i] = v;
    }
    __shared__ float sm[THREADS / 32][NACC];
    const int warp = tid >> 5, lane = tid & 31;
    if (lane == 0) {
#pragma unroll
        for (int i = 0; i < NACC; i++) sm[warp][i] = acc[i];
    }
    __syncthreads();
    if (tid < NACC) {
        float s = 0.0f;
#pragma unroll
        for (int w = 0; w < THREADS / 32; w++) s += sm[w][tid];
        g_scratch[((size_t)b * BPB + blockIdx.x) * ROW + tid] = s;
    }
}

// Parallel finalize: 64 blocks (one per batch) x 64 threads.
// Each block reduces its 25x23 partials (~2.3KB, L2-hot) and computes the
// per-batch loss; the LAST block (atomic counter) sums the 64 losses.
__global__ __launch_bounds__(64)
void hung_final(float* __restrict__ out)
{
    const int b = blockIdx.x;
    const int tid = threadIdx.x;

    __shared__ float sa[NACC];
    __shared__ unsigned int s_last;

    if (tid < NACC) {
        float v = 0.0f;
#pragma unroll
        for (int j = 0; j < BPB; j++)
            v += g_scratch[((size_t)b * BPB + j) * ROW + tid];
        sa[tid] = v;
    }
    __syncthreads();

    if (tid == 0) {
        const float* a = sa;
        const float Tfg   = a[22];
        const float Tbg   = (float)Nc - Tfg;
        const float spsum = a[20];
        const float tabs  = a[21];
        float sumXS = 0.0f, sumXF = 0.0f;
        float best = 3.4e38f, selXS = 0.0f, selXF = 0.0f;
#pragma unroll
        for (int k = 0; k < Kc; k++) {
            const float S  = a[k*4+0];
            const float I  = a[k*4+1];
            const float XS = a[k*4+2];
            const float XF = a[k*4+3];
            const float Ib = S - I;
            const float cfg = 1.0f - I  / (S + Tfg - I  + 1e-6f);
            const float cbg = 1.0f - Ib / (S + Tbg - Ib + 1e-6f);
            const float score = cfg - cbg;   // perm cost differs only by this term
            if (score < best) { best = score; selXS = XS; selXF = XF; }  // ties -> smallest k
            sumXS += XS; sumXF += XF;
        }
        const float Ctot = spsum + 0.5f * (sumXS + tabs);  // sum max(x,0) + sum softplus
        // loss_b = Ctot - [XF_k0 + sum_{k!=k0}(XS_k - XF_k)]
        g_loss[b] = Ctot - sumXS + sumXF + selXS - 2.0f * selXF;
        __threadfence();
        s_last = (atomicInc(&g_cnt, Bc - 1) == Bc - 1) ? 1u : 0u;
    }
    __syncthreads();
    if (s_last == 0u) return;

    // Last block: sum the 64 per-batch losses (L2-resident).
    float l = (tid < Bc) ? __ldcg(&g_loss[tid]) : 0.0f;
#pragma unroll
    for (int o = 16; o > 0; o >>= 1) l += __shfl_xor_sync(0xffffffffu, l, o);
    __shared__ float wsum[2];
    if ((tid & 31) == 0) wsum[tid >> 5] = l;
    __syncthreads();
    if (tid == 0)
        out[0] = (wsum[0] + wsum[1]) * (1.0f / ((float)Bc * (float)Kc * (float)Nc));
}

extern "C" void kernel_launch(void* const* d_in, const int* in_sizes, int n_in,
                              void* d_out, int out_size)
{
    // metadata order: fg_logits (unused by reference), slot_logits, target
    const float* slot = (const float*)d_in[1];
    const float* tgt  = (const float*)d_in[2];
    float* out = (float*)d_out;

    dim3 grid(BPB, Bc);
    hung_main<<<grid, THREADS>>>(slot, tgt);
    hung_final<<<Bc, 64>>>(out);
}

// round 11
// speedup vs baseline: 1.2185x; 1.0468x over previous
#include <cuda_runtime.h>

// Problem constants
#define Bc 64
#define Kc 5
#define Hc 320
#define Wc 320
#define Nc (Hc * Wc)        // 102400 pixels per (b,k)
#define NGc (Nc / 4)        // 25600 float4 groups
#define BPB 25              // blocks per batch; each block owns 1024 groups
#define THREADS 256
#define TOTAL_BLOCKS (Bc * BPB)
#define NACC 23             // 5*(S,I,XS,XF) + spsum + tabs + tfg
#define ROW 24              // scratch row stride (floats)

// Per-block partial sums: [b*BPB+block][ROW]. Overwritten every launch.
__device__ float g_scratch[TOTAL_BLOCKS * ROW];
// Per-batch losses + last-block counter for the finalize kernel.
__device__ float g_loss[Bc];
// atomicInc with limit Bc-1 wraps to 0 after exactly Bc increments ->
// self-resetting across graph replays.
__device__ unsigned int g_cnt = 0;

// Per-element update — EXACT R8 form. 3 MUFU (EX2, RCP, LG2) ~= 22us chip-wide.
// MUFU.RCP is mandatory: a 1.2e-5 approx reciprocal flipped a near-tied argmin
// (rel_err 7.4e-8 -> 4.4e-4 in R10). Moving ops off MUFU onto fma is a wash
// (fma pipe just becomes the ~24us pipe instead).
// BCE identity: sum max(x,0) = 0.5*(sum x + sum |x|) -> no per-k softplus acc.
__device__ __forceinline__ void elem(float x, float fg,
                                     float& S, float& I, float& XS, float& XF,
                                     float& spsum, float& tabs)
{
    const float t  = fabsf(x);
    const float e  = __expf(-t);                 // FMUL + MUFU.EX2
    const float u  = 1.0f + e;
    const float rc = __fdividef(1.0f, u);        // MUFU.RCP
    const float p  = (x >= 0.0f) ? rc : (1.0f - rc);   // sigmoid(x)
    const float sp = __logf(u);                  // log1p(e) = MUFU.LG2 + FMUL

    spsum += sp;
    tabs  += t;
    S     += p;
    I      = fmaf(p, fg, I);
    XS    += x;
    XF     = fmaf(x, fg, XF);
}

#define ELEM4(xv, fgv, k) \
    elem((xv).x, (fgv).x, acc[(k)*4+0], acc[(k)*4+1], acc[(k)*4+2], acc[(k)*4+3], acc[20], acc[21]); \
    elem((xv).y, (fgv).y, acc[(k)*4+0], acc[(k)*4+1], acc[(k)*4+2], acc[(k)*4+3], acc[20], acc[21]); \
    elem((xv).z, (fgv).z, acc[(k)*4+0], acc[(k)*4+1], acc[(k)*4+2], acc[(k)*4+3], acc[20], acc[21]); \
    elem((xv).w, (fgv).w, acc[(k)*4+0], acc[(k)*4+1], acc[(k)*4+2], acc[(k)*4+3], acc[20], acc[21]);

// Hot-loop kernel: stays standalone (fusion => regs=48 serialized loads, or
// regs=128 occupancy collapse). Identical to the proven R8 kernel except for
// the PDL trigger after the scratch store.
__global__ __launch_bounds__(THREADS)
void hung_main(const float* __restrict__ slot, const float* __restrict__ tgt)
{
    const int b = blockIdx.y;
    const int tid = threadIdx.x;

    float acc[NACC];
#pragma unroll
    for (int i = 0; i < NACC; i++) acc[i] = 0.0f;

    const float4* tg4 = reinterpret_cast<const float4*>(tgt) + (size_t)b * NGc;
    const float4* sl4 = reinterpret_cast<const float4*>(slot) + (size_t)b * Kc * NGc;

    const int base = blockIdx.x * (NGc / BPB);   // 1024 groups per block

    // Two iterations; each explicitly batches 12 independent LDG.128s before
    // any compute (MLP=12). unroll 1 stops ptxas from merging iterations into
    // a 24-deep front batch (L1tex-queue contention, R4 = 54us).
#pragma unroll 1
    for (int it = 0; it < 2; it++) {
        const int g0 = base + it * (2 * THREADS) + tid;
        const int g1 = g0 + THREADS;

        const float4 fgA = __ldg(&tg4[g0]);
        const float4 fgB = __ldg(&tg4[g1]);
        float4 xa[Kc], xb[Kc];
#pragma unroll
        for (int k = 0; k < Kc; k++) {
            xa[k] = __ldg(&sl4[(size_t)k * NGc + g0]);
            xb[k] = __ldg(&sl4[(size_t)k * NGc + g1]);
        }

        acc[22] += ((fgA.x + fgA.y) + (fgA.z + fgA.w))
                 + ((fgB.x + fgB.y) + (fgB.z + fgB.w));   // tfg
#pragma unroll
        for (int k = 0; k < Kc; k++) {
            ELEM4(xa[k], fgA, k)
            ELEM4(xb[k], fgB, k)
        }
    }

    // Block reduction: warp shuffle then cross-warp via shared (deterministic).
#pragma unroll
    for (int i = 0; i < NACC; i++) {
        float v = acc[i];
#pragma unroll
        for (int o = 16; o > 0; o >>= 1) v += __shfl_xor_sync(0xffffffffu, v, o);
        acc[i] = v;
    }
    __shared__ float sm[THREADS / 32][NACC];
    const int warp = tid >> 5, lane = tid & 31;
    if (lane == 0) {
#pragma unroll
        for (int i = 0; i < NACC; i++) sm[warp][i] = acc[i];
    }
    __syncthreads();
    if (tid < NACC) {
        float s = 0.0f;
#pragma unroll
        for (int w = 0; w < THREADS / 32; w++) s += sm[w][tid];
        g_scratch[((size_t)b * BPB + blockIdx.x) * ROW + tid] = s;
    }

    // PDL: this block's contribution is fully stored; let the dependent
    // finalize grid proceed once every block has triggered (or exited).
    __syncthreads();
    if (tid == 0) {
        __threadfence();
        cudaTriggerProgrammaticLaunchCompletion();
    }
}

// Parallel finalize: 64 blocks (one per batch) x 64 threads, launched with
// programmatic stream serialization so its launch latency overlaps main's
// drain. cudaGridDependencySynchronize() gates the g_scratch reads.
__global__ __launch_bounds__(64)
void hung_final(float* __restrict__ out)
{
    const int b = blockIdx.x;
    const int tid = threadIdx.x;

    __shared__ float sa[NACC];
    __shared__ unsigned int s_last;

    cudaGridDependencySynchronize();   // wait for hung_main's writes

    if (tid < NACC) {
        float v = 0.0f;
#pragma unroll
        for (int j = 0; j < BPB; j++)
            v += g_scratch[((size_t)b * BPB + j) * ROW + tid];
        sa[tid] = v;
    }
    __syncthreads();

    if (tid == 0) {
        const float* a = sa;
        const float Tfg   = a[22];
        const float Tbg   = (float)Nc - Tfg;
        const float spsum = a[20];
        const float tabs  = a[21];
        float sumXS = 0.0f, sumXF = 0.0f;
        float best = 3.4e38f, selXS = 0.0f, selXF = 0.0f;
#pragma unroll
        for (int k = 0; k < Kc; k++) {
            const float S  = a[k*4+0];
            const float I  = a[k*4+1];
            const float XS = a[k*4+2];
            const float XF = a[k*4+3];
            const float Ib = S - I;
            const float cfg = 1.0f - I  / (S + Tfg - I  + 1e-6f);
            const float cbg = 1.0f - Ib / (S + Tbg - Ib + 1e-6f);
            const float score = cfg - cbg;   // perm cost differs only by this term
            if (score < best) { best = score; selXS = XS; selXF = XF; }  // ties -> smallest k
            sumXS += XS; sumXF += XF;
        }
        const float Ctot = spsum + 0.5f * (sumXS + tabs);  // sum max(x,0) + sum softplus
        // loss_b = Ctot - [XF_k0 + sum_{k!=k0}(XS_k - XF_k)]
        g_loss[b] = Ctot - sumXS + sumXF + selXS - 2.0f * selXF;
        __threadfence();
        s_last = (atomicInc(&g_cnt, Bc - 1) == Bc - 1) ? 1u : 0u;
    }
    __syncthreads();
    if (s_last == 0u) return;

    // Last block: sum the 64 per-batch losses (L2-resident).
    float l = (tid < Bc) ? __ldcg(&g_loss[tid]) : 0.0f;
#pragma unroll
    for (int o = 16; o > 0; o >>= 1) l += __shfl_xor_sync(0xffffffffu, l, o);
    __shared__ float wsum[2];
    if ((tid & 31) == 0) wsum[tid >> 5] = l;
    __syncthreads();
    if (tid == 0)
        out[0] = (wsum[0] + wsum[1]) * (1.0f / ((float)Bc * (float)Kc * (float)Nc));
}

extern "C" void kernel_launch(void* const* d_in, const int* in_sizes, int n_in,
                              void* d_out, int out_size)
{
    // metadata order: fg_logits (unused by reference), slot_logits, target
    const float* slot = (const float*)d_in[1];
    const float* tgt  = (const float*)d_in[2];
    float* out = (float*)d_out;

    dim3 grid(BPB, Bc);
    hung_main<<<grid, THREADS>>>(slot, tgt);

    // Finalize with programmatic dependent launch: overlaps its launch/arming
    // with hung_main's drain; the grid-dependency sync provides ordering.
    cudaLaunchConfig_t cfg = {};
    cfg.gridDim  = dim3(Bc, 1, 1);
    cfg.blockDim = dim3(64, 1, 1);
    cudaLaunchAttribute attr[1];
    attr[0].id = cudaLaunchAttributeProgrammaticStreamSerialization;
    attr[0].val.programmaticStreamSerializationAllowed = 1;
    cfg.attrs = attr;
    cfg.numAttrs = 1;
    cudaLaunchKernelEx(&cfg, hung_final, out);
}